// round 14
// baseline (speedup 1.0000x reference)
#include <cuda_runtime.h>
#include <cstdint>

#define D        64
#define ITERS    4
#define OUTC     ((ITERS + 1) * D)   // 320 output columns
#define N_MAX    50016               // padded
#define E_MAX    800000
#define TPB      256

// -------- scratch (__device__ globals; no allocation allowed) --------
// Zero-initialized at module load. scan_kernel re-zeroes g_deg each call
// (after consuming it), so graph replays stay deterministic with no
// dedicated init kernel.
__device__ int g_deg[N_MAX];          // in-degree
__device__ int g_rowptr[N_MAX + 1];   // CSR row pointers (by dst)
__device__ int g_cursor[N_MAX];       // placement cursors (rewritten by scan)
__device__ int g_col[E_MAX];          // CSR columns (src grouped by dst)

// Block-local dtype detect: majority vote over the first 64 (lo,hi) word
// pairs of the edge_index buffer (valid prefix for either dtype). int64
// data has hi-word == 0 for all ids < 2^31; int32 data has random ids
// there (P(zero) ~ 2e-5). Returns 1 if int64.
__device__ __forceinline__ int detect_is64(const int* __restrict__ p32,
                                           int* __restrict__ sh_zc) {
    if (threadIdx.x == 0) *sh_zc = 0;
    __syncthreads();
    if (threadIdx.x < 64)
        if (p32[2 * threadIdx.x + 1] == 0) atomicAdd(sh_zc, 1);
    __syncthreads();
    return (*sh_zc >= 48) ? 1 : 0;
}

// ---------------- kernels ----------------

// Fused: degree histogram (edge part) + copy x into out slab 0 (node part).
// Launched with max(E, 16*N) threads (equal here: 800k).
__global__ void convert_copy_kernel(const int* __restrict__ p32,
                                    const float* __restrict__ x,
                                    float* __restrict__ out,
                                    int n_edges, int n_nodes) {
    __shared__ int sh_zc;
    int is64 = detect_is64(p32, &sh_zc);

    int t = blockIdx.x * blockDim.x + threadIdx.x;

    if (t < n_edges) {
        int d = is64 ? p32[2 * ((size_t)n_edges + t)] : p32[n_edges + t];
        atomicAdd(&g_deg[d], 1);
    }

    int i = t >> 4;
    int lane = t & 15;                    // 16 lanes x float4 = 64 floats
    if (i < n_nodes) {
        float4 v = reinterpret_cast<const float4*>(x + (size_t)i * D)[lane];
        reinterpret_cast<float4*>(out + (size_t)i * OUTC)[lane] = v;
    }
}

// Single-block two-pass exclusive scan of g_deg -> g_rowptr (+ cursors).
// Re-zeroes g_deg after its final use so the next graph replay starts clean.
__global__ void scan_kernel(int n_nodes, int n_edges) {
    __shared__ int sm[TPB];
    int chunk = (n_nodes + TPB - 1) / TPB;
    int base = threadIdx.x * chunk;
    int lim = min(base + chunk, n_nodes);

    int sum = 0;
    for (int i = base; i < lim; i++) sum += g_deg[i];
    sm[threadIdx.x] = sum;
    __syncthreads();
    for (int off = 1; off < TPB; off <<= 1) {
        int v = (threadIdx.x >= off) ? sm[threadIdx.x - off] : 0;
        __syncthreads();
        sm[threadIdx.x] += v;
        __syncthreads();
    }
    int run = sm[threadIdx.x] - sum;      // exclusive offset for this chunk
    for (int i = base; i < lim; i++) {
        int dv = g_deg[i];
        g_rowptr[i] = run;
        g_cursor[i] = run;
        run += dv;
        g_deg[i] = 0;                     // reset for next replay
    }
    if (threadIdx.x == TPB - 1) g_rowptr[n_nodes] = n_edges;
}

// Place src ids into CSR order (by dst), reading edge_index directly.
__global__ void place_kernel(const int* __restrict__ p32, int n_edges) {
    __shared__ int sh_zc;
    int is64 = detect_is64(p32, &sh_zc);

    int e = blockIdx.x * blockDim.x + threadIdx.x;
    if (e >= n_edges) return;
    int s, d;
    if (is64) {
        s = p32[2 * e];
        d = p32[2 * ((size_t)n_edges + e)];
    } else {
        s = p32[e];
        d = p32[n_edges + e];
    }
    int pos = atomicAdd(&g_cursor[d], 1);
    g_col[pos] = s;
}

// Fused pull + combine (fp32 gather, R9-proven config):
//   out_k[i] = 0.5 * ( out_{k-1}[i] + (1/max(deg,1)) * sum_j out_{k-1}[col[j]] )
// 16 threads per node, float4 per thread; neighbor sum in registers.
__global__ void pull_kernel(const float* __restrict__ xin,   // out + (k-1)*D
                            float* __restrict__ xout,        // out + k*D
                            int n_nodes) {
    int t = blockIdx.x * blockDim.x + threadIdx.x;
    int i = t >> 4;
    int lane = t & 15;
    if (i >= n_nodes) return;
    int start = g_rowptr[i];
    int end   = g_rowptr[i + 1];

    float4 acc = make_float4(0.f, 0.f, 0.f, 0.f);
#pragma unroll 4
    for (int j = start; j < end; j++) {
        int s = __ldg(&g_col[j]);
        float4 v = reinterpret_cast<const float4*>(xin + (size_t)s * OUTC)[lane];
        acc.x += v.x; acc.y += v.y; acc.z += v.z; acc.w += v.w;
    }

    int deg = end - start;
    float inv = 1.0f / (float)(deg > 0 ? deg : 1);
    float4 xv = reinterpret_cast<const float4*>(xin + (size_t)i * OUTC)[lane];
    float4 r;
    r.x = 0.5f * fmaf(acc.x, inv, xv.x);
    r.y = 0.5f * fmaf(acc.y, inv, xv.y);
    r.z = 0.5f * fmaf(acc.z, inv, xv.z);
    r.w = 0.5f * fmaf(acc.w, inv, xv.w);
    reinterpret_cast<float4*>(xout + (size_t)i * OUTC)[lane] = r;
}

// ---------------- launch ----------------

extern "C" void kernel_launch(void* const* d_in, const int* in_sizes, int n_in,
                              void* d_out, int out_size) {
    const float* x   = (const float*)d_in[0];
    const int*   p32 = (const int*)d_in[1];
    float*       out = (float*)d_out;

    const int n_nodes = in_sizes[0] / D;      // 50000
    const int n_edges = in_sizes[1] / 2;      // 800000

    const int big      = (n_edges > n_nodes * 16) ? n_edges : n_nodes * 16;
    const int nb_big   = (big + TPB - 1) / TPB;
    const int nb_edges = (n_edges + TPB - 1) / TPB;

    // 0: histogram + slab-0 copy (g_deg zeroed by previous scan / load-init)
    convert_copy_kernel<<<nb_big, TPB>>>(p32, x, out, n_edges, n_nodes);

    // 1: rowptr scan (single block), also resets g_deg for next replay
    scan_kernel<<<1, TPB>>>(n_nodes, n_edges);

    // 2: CSR placement straight from edge_index
    place_kernel<<<nb_edges, TPB>>>(p32, n_edges);

    // 3..6: WL iterations (fused pull + combine). Launch index 3 == pull #1,
    // which is what ncu's sampled launch will now profile.
    {
        int threads = n_nodes * 16;
        int blocks = (threads + TPB - 1) / TPB;
        for (int k = 1; k <= ITERS; k++) {
            pull_kernel<<<blocks, TPB>>>(out + (size_t)(k - 1) * D,
                                         out + (size_t)k * D,
                                         n_nodes);
        }
    }
}

// round 15
// speedup vs baseline: 2.1893x; 2.1893x over previous
#include <cuda_runtime.h>
#include <cuda_fp16.h>
#include <cstdint>

#define D        64
#define ITERS    4
#define OUTC     ((ITERS + 1) * D)   // 320 output columns
#define N_MAX    50016               // padded
#define E_MAX    800000
#define TPB      256
#define SCAN_B   256

// -------- scratch (__device__ globals; no allocation allowed) --------
// Zero-initialized at module load; g_deg is re-zeroed by scan3 each call so
// graph replays stay deterministic.
__device__ int    g_deg[N_MAX];          // in-degree
__device__ int    g_rowptr[N_MAX + 1];   // CSR row pointers (by dst)
__device__ int    g_cursor[N_MAX];       // placement cursors
__device__ int    g_blocksum[SCAN_B];    // scan partials (<=256 blocks)
__device__ int    g_blockoff[SCAN_B];
__device__ int    g_col[E_MAX];          // CSR columns (src grouped by dst)
__device__ __half g_xh0[N_MAX * D];      // fp16 shadow (ping)
__device__ __half g_xh1[N_MAX * D];      // fp16 shadow (pong)

// Block-local dtype detect: majority vote over the first 64 (lo,hi) pairs of
// the edge_index buffer (valid prefix for either dtype). int64 ids < 2^31
// have hi-word == 0; int32 data has random ids there. Returns 1 if int64.
__device__ __forceinline__ int detect_is64(const int* __restrict__ p32,
                                           int* __restrict__ sh_zc) {
    if (threadIdx.x == 0) *sh_zc = 0;
    __syncthreads();
    if (threadIdx.x < 64)
        if (p32[2 * threadIdx.x + 1] == 0) atomicAdd(sh_zc, 1);
    __syncthreads();
    return (*sh_zc >= 48) ? 1 : 0;
}

// ---------------- kernels ----------------

// Fused: degree histogram (edge part) + copy x into out slab 0 (fp32) and
// g_xh0 (fp16) (node part). Launched with max(E, 16*N) threads.
__global__ void convert_copy_kernel(const int* __restrict__ p32,
                                    const float* __restrict__ x,
                                    float* __restrict__ out,
                                    int n_edges, int n_nodes) {
    __shared__ int sh_zc;
    int is64 = detect_is64(p32, &sh_zc);

    int t = blockIdx.x * blockDim.x + threadIdx.x;

    if (t < n_edges) {
        int d = is64 ? p32[2 * ((size_t)n_edges + t)] : p32[n_edges + t];
        atomicAdd(&g_deg[d], 1);
    }

    int i = t >> 4;
    int lane = t & 15;                    // 16 lanes x float4 = 64 floats
    if (i < n_nodes) {
        float4 v = reinterpret_cast<const float4*>(x + (size_t)i * D)[lane];
        reinterpret_cast<float4*>(out + (size_t)i * OUTC)[lane] = v;
        __half2 h0 = __float22half2_rn(make_float2(v.x, v.y));
        __half2 h1 = __float22half2_rn(make_float2(v.z, v.w));
        uint2 hw;
        hw.x = *reinterpret_cast<unsigned*>(&h0);
        hw.y = *reinterpret_cast<unsigned*>(&h1);
        reinterpret_cast<uint2*>(g_xh0 + (size_t)i * D)[lane] = hw;
    }
}

// --- 3-kernel multi-block exclusive scan of g_deg -> g_rowptr (R9-proven;
// the R11..R14 single-block scan was a ~95 us serial bottleneck) ---
__global__ void scan1_kernel(int n_nodes) {
    __shared__ int sm[SCAN_B];
    int i = blockIdx.x * SCAN_B + threadIdx.x;
    int v = (i < n_nodes) ? g_deg[i] : 0;
    sm[threadIdx.x] = v;
    __syncthreads();
    for (int off = 1; off < SCAN_B; off <<= 1) {
        int t = (threadIdx.x >= off) ? sm[threadIdx.x - off] : 0;
        __syncthreads();
        sm[threadIdx.x] += t;
        __syncthreads();
    }
    if (i < n_nodes) g_rowptr[i] = sm[threadIdx.x] - v;   // exclusive
    if (threadIdx.x == SCAN_B - 1) g_blocksum[blockIdx.x] = sm[threadIdx.x];
}

__global__ void scan2_kernel(int nblocks) {   // <<<1, SCAN_B>>>
    __shared__ int sm[SCAN_B];
    int v = (threadIdx.x < nblocks) ? g_blocksum[threadIdx.x] : 0;
    sm[threadIdx.x] = v;
    __syncthreads();
    for (int off = 1; off < SCAN_B; off <<= 1) {
        int t = (threadIdx.x >= off) ? sm[threadIdx.x - off] : 0;
        __syncthreads();
        sm[threadIdx.x] += t;
        __syncthreads();
    }
    g_blockoff[threadIdx.x] = sm[threadIdx.x] - v;        // exclusive
}

__global__ void scan3_kernel(int n_nodes, int n_edges) {
    int i = blockIdx.x * blockDim.x + threadIdx.x;
    if (i < n_nodes) {
        int r = g_rowptr[i] + g_blockoff[i / SCAN_B];
        g_rowptr[i] = r;
        g_cursor[i] = r;
        g_deg[i] = 0;                     // reset for next graph replay
    }
    if (i == n_nodes) g_rowptr[n_nodes] = n_edges;
}

// Place src ids into CSR order (by dst), reading edge_index directly.
__global__ void place_kernel(const int* __restrict__ p32, int n_edges) {
    __shared__ int sh_zc;
    int is64 = detect_is64(p32, &sh_zc);

    int e = blockIdx.x * blockDim.x + threadIdx.x;
    if (e >= n_edges) return;
    int s, d;
    if (is64) {
        s = p32[2 * e];
        d = p32[2 * ((size_t)n_edges + e)];
    } else {
        s = p32[e];
        d = p32[n_edges + e];
    }
    int pos = atomicAdd(&g_cursor[d], 1);
    g_col[pos] = s;
}

// Fused pull + combine, fp16 gather, 16 threads/node. Ping-pong shadows
// resolved in device code via parity.
//   out_k[i] = 0.5 * ( out_{k-1}[i] + (1/max(deg,1)) * sum_j xh[col[j]] )
__global__ void pull_kernel(const float* __restrict__ xin,   // out + (k-1)*D
                            float* __restrict__ xout,        // out + k*D
                            int n_nodes, int parity, int write_half) {
    const __half* __restrict__ xh_in  = parity ? g_xh1 : g_xh0;
    __half*       __restrict__ xh_out = parity ? g_xh0 : g_xh1;

    int t = blockIdx.x * blockDim.x + threadIdx.x;
    int i = t >> 4;
    int lane = t & 15;
    if (i >= n_nodes) return;
    int start = g_rowptr[i];
    int end   = g_rowptr[i + 1];

    float a0 = 0.f, a1 = 0.f, a2 = 0.f, a3 = 0.f;

#pragma unroll 8
    for (int j = start; j < end; j++) {
        int s = __ldg(&g_col[j]);
        uint2 hw = reinterpret_cast<const uint2*>(xh_in + (size_t)s * D)[lane];
        float2 f0 = __half22float2(*reinterpret_cast<__half2*>(&hw.x));
        float2 f1 = __half22float2(*reinterpret_cast<__half2*>(&hw.y));
        a0 += f0.x; a1 += f0.y; a2 += f1.x; a3 += f1.y;
    }

    int deg = end - start;
    float inv = 1.0f / (float)(deg > 0 ? deg : 1);
    float4 xv = reinterpret_cast<const float4*>(xin + (size_t)i * OUTC)[lane];
    float4 r;
    r.x = 0.5f * fmaf(a0, inv, xv.x);
    r.y = 0.5f * fmaf(a1, inv, xv.y);
    r.z = 0.5f * fmaf(a2, inv, xv.z);
    r.w = 0.5f * fmaf(a3, inv, xv.w);
    reinterpret_cast<float4*>(xout + (size_t)i * OUTC)[lane] = r;

    if (write_half) {
        __half2 h0 = __float22half2_rn(make_float2(r.x, r.y));
        __half2 h1 = __float22half2_rn(make_float2(r.z, r.w));
        uint2 hw;
        hw.x = *reinterpret_cast<unsigned*>(&h0);
        hw.y = *reinterpret_cast<unsigned*>(&h1);
        reinterpret_cast<uint2*>(xh_out + (size_t)i * D)[lane] = hw;
    }
}

// ---------------- launch ----------------

extern "C" void kernel_launch(void* const* d_in, const int* in_sizes, int n_in,
                              void* d_out, int out_size) {
    const float* x   = (const float*)d_in[0];
    const int*   p32 = (const int*)d_in[1];
    float*       out = (float*)d_out;

    const int n_nodes = in_sizes[0] / D;      // 50000
    const int n_edges = in_sizes[1] / 2;      // 800000

    const int big       = (n_edges > n_nodes * 16) ? n_edges : n_nodes * 16;
    const int nb_big    = (big + TPB - 1) / TPB;
    const int nb_edges  = (n_edges + TPB - 1) / TPB;
    const int nb_scan   = (n_nodes + SCAN_B - 1) / SCAN_B;    // 196
    const int nb_nodes1 = (n_nodes + 1 + TPB - 1) / TPB;

    // 0: histogram + slab-0 copies (fp32 + fp16)
    convert_copy_kernel<<<nb_big, TPB>>>(p32, x, out, n_edges, n_nodes);

    // 1-3: multi-block rowptr scan (+ cursor init, g_deg reset)
    scan1_kernel<<<nb_scan, SCAN_B>>>(n_nodes);
    scan2_kernel<<<1, SCAN_B>>>(nb_scan);
    scan3_kernel<<<nb_nodes1, TPB>>>(n_nodes, n_edges);

    // 4: CSR placement straight from edge_index
    place_kernel<<<nb_edges, TPB>>>(p32, n_edges);

    // 5-8: WL iterations (fused pull + combine, fp16 gather, ping-pong)
    {
        int threads = n_nodes * 16;
        int blocks = (threads + TPB - 1) / TPB;
        for (int k = 1; k <= ITERS; k++) {
            pull_kernel<<<blocks, TPB>>>(out + (size_t)(k - 1) * D,
                                         out + (size_t)k * D,
                                         n_nodes, (k - 1) & 1,
                                         (k < ITERS) ? 1 : 0);
        }
    }
}

// round 16
// speedup vs baseline: 2.2325x; 1.0197x over previous
#include <cuda_runtime.h>
#include <cuda_fp16.h>
#include <cstdint>

#define D        64
#define ITERS    4
#define OUTC     ((ITERS + 1) * D)   // 320 output columns
#define N_MAX    50016               // padded
#define E_MAX    800000
#define TPB      256
#define SCAN_B   256
#define PLACE_ILP 4

// -------- scratch (__device__ globals; no allocation allowed) --------
// Zero-initialized at module load; g_deg is re-zeroed by scan23 each call so
// graph replays stay deterministic.
__device__ int    g_deg[N_MAX];          // in-degree
__device__ int    g_rowptr[N_MAX + 1];   // CSR row pointers (by dst)
__device__ int    g_cursor[N_MAX];       // placement cursors
__device__ int    g_blocksum[SCAN_B];    // scan partials (<=256 blocks)
__device__ int    g_col[E_MAX];          // CSR columns (src grouped by dst)
__device__ __half g_xh0[N_MAX * D];      // fp16 shadow (ping)
__device__ __half g_xh1[N_MAX * D];      // fp16 shadow (pong)

// Block-local dtype detect: majority vote over the first 64 (lo,hi) pairs of
// the edge_index buffer (valid prefix for either dtype). int64 ids < 2^31
// have hi-word == 0; int32 data has random ids there. Returns 1 if int64.
__device__ __forceinline__ int detect_is64(const int* __restrict__ p32,
                                           int* __restrict__ sh_zc) {
    if (threadIdx.x == 0) *sh_zc = 0;
    __syncthreads();
    if (threadIdx.x < 64)
        if (p32[2 * threadIdx.x + 1] == 0) atomicAdd(sh_zc, 1);
    __syncthreads();
    return (*sh_zc >= 48) ? 1 : 0;
}

// ---------------- kernels ----------------

// Fused: degree histogram (edge part) + copy x into out slab 0 (fp32) and
// g_xh0 (fp16) (node part). Launched with max(E, 16*N) threads.
__global__ void convert_copy_kernel(const int* __restrict__ p32,
                                    const float* __restrict__ x,
                                    float* __restrict__ out,
                                    int n_edges, int n_nodes) {
    __shared__ int sh_zc;
    int is64 = detect_is64(p32, &sh_zc);

    int t = blockIdx.x * blockDim.x + threadIdx.x;

    if (t < n_edges) {
        int d = is64 ? p32[2 * ((size_t)n_edges + t)] : p32[n_edges + t];
        atomicAdd(&g_deg[d], 1);
    }

    int i = t >> 4;
    int lane = t & 15;                    // 16 lanes x float4 = 64 floats
    if (i < n_nodes) {
        float4 v = reinterpret_cast<const float4*>(x + (size_t)i * D)[lane];
        reinterpret_cast<float4*>(out + (size_t)i * OUTC)[lane] = v;
        __half2 h0 = __float22half2_rn(make_float2(v.x, v.y));
        __half2 h1 = __float22half2_rn(make_float2(v.z, v.w));
        uint2 hw;
        hw.x = *reinterpret_cast<unsigned*>(&h0);
        hw.y = *reinterpret_cast<unsigned*>(&h1);
        reinterpret_cast<uint2*>(g_xh0 + (size_t)i * D)[lane] = hw;
    }
}

// --- exclusive scan of g_deg -> g_rowptr, 2 kernels ---
// scan1: per-block inclusive scan + block totals.
__global__ void scan1_kernel(int n_nodes) {
    __shared__ int sm[SCAN_B];
    int i = blockIdx.x * SCAN_B + threadIdx.x;
    int v = (i < n_nodes) ? g_deg[i] : 0;
    sm[threadIdx.x] = v;
    __syncthreads();
    for (int off = 1; off < SCAN_B; off <<= 1) {
        int t = (threadIdx.x >= off) ? sm[threadIdx.x - off] : 0;
        __syncthreads();
        sm[threadIdx.x] += t;
        __syncthreads();
    }
    if (i < n_nodes) g_rowptr[i] = sm[threadIdx.x] - v;   // exclusive in-block
    if (threadIdx.x == SCAN_B - 1) g_blocksum[blockIdx.x] = sm[threadIdx.x];
}

// scan23 (merged R15 scan2+scan3): block b covers scan1-block b's nodes, so
// it needs only the scalar prefix sum_{j<b} blocksum[j] — computed with an
// in-block shared reduction (one load per thread). Also initializes cursors
// and resets g_deg for the next graph replay.
__global__ void scan23_kernel(int n_nodes, int n_edges, int nblocks) {
    __shared__ int sm[SCAN_B];
    int b = blockIdx.x;
    int v = (threadIdx.x < b && threadIdx.x < nblocks)
                ? g_blocksum[threadIdx.x] : 0;
    sm[threadIdx.x] = v;
    __syncthreads();
    for (int off = SCAN_B / 2; off > 0; off >>= 1) {
        if (threadIdx.x < off) sm[threadIdx.x] += sm[threadIdx.x + off];
        __syncthreads();
    }
    int boff = sm[0];

    int i = b * SCAN_B + threadIdx.x;
    if (i < n_nodes) {
        int r = g_rowptr[i] + boff;
        g_rowptr[i] = r;
        g_cursor[i] = r;
        g_deg[i] = 0;                     // reset for next replay
    }
    if (i == n_nodes) g_rowptr[n_nodes] = n_edges;
}

// Place src ids into CSR order (by dst), reading edge_index directly.
// 4 independent edges per thread: the returning atomicAdd has ~318 cyc
// latency and one chain per thread left this kernel latency-exposed
// (occ 78%, issue 4%); 4-way MLP amortizes it.
__global__ void place_kernel(const int* __restrict__ p32, int n_edges) {
    __shared__ int sh_zc;
    int is64 = detect_is64(p32, &sh_zc);

    int base = (blockIdx.x * blockDim.x + threadIdx.x) * PLACE_ILP;
    int s[PLACE_ILP], d[PLACE_ILP];
#pragma unroll
    for (int u = 0; u < PLACE_ILP; u++) {
        int e = base + u;
        if (e < n_edges) {
            if (is64) {
                s[u] = p32[2 * e];
                d[u] = p32[2 * ((size_t)n_edges + e)];
            } else {
                s[u] = p32[e];
                d[u] = p32[n_edges + e];
            }
        }
    }
    int pos[PLACE_ILP];
#pragma unroll
    for (int u = 0; u < PLACE_ILP; u++) {
        int e = base + u;
        if (e < n_edges) pos[u] = atomicAdd(&g_cursor[d[u]], 1);
    }
#pragma unroll
    for (int u = 0; u < PLACE_ILP; u++) {
        int e = base + u;
        if (e < n_edges) g_col[pos[u]] = s[u];
    }
}

// Fused pull + combine, fp16 gather, 16 threads/node. Ping-pong shadows
// resolved in device code via parity.
//   out_k[i] = 0.5 * ( out_{k-1}[i] + (1/max(deg,1)) * sum_j xh[col[j]] )
__global__ void pull_kernel(const float* __restrict__ xin,   // out + (k-1)*D
                            float* __restrict__ xout,        // out + k*D
                            int n_nodes, int parity, int write_half) {
    const __half* __restrict__ xh_in  = parity ? g_xh1 : g_xh0;
    __half*       __restrict__ xh_out = parity ? g_xh0 : g_xh1;

    int t = blockIdx.x * blockDim.x + threadIdx.x;
    int i = t >> 4;
    int lane = t & 15;
    if (i >= n_nodes) return;
    int start = g_rowptr[i];
    int end   = g_rowptr[i + 1];

    float a0 = 0.f, a1 = 0.f, a2 = 0.f, a3 = 0.f;

#pragma unroll 8
    for (int j = start; j < end; j++) {
        int s = __ldg(&g_col[j]);
        uint2 hw = reinterpret_cast<const uint2*>(xh_in + (size_t)s * D)[lane];
        float2 f0 = __half22float2(*reinterpret_cast<__half2*>(&hw.x));
        float2 f1 = __half22float2(*reinterpret_cast<__half2*>(&hw.y));
        a0 += f0.x; a1 += f0.y; a2 += f1.x; a3 += f1.y;
    }

    int deg = end - start;
    float inv = 1.0f / (float)(deg > 0 ? deg : 1);
    float4 xv = reinterpret_cast<const float4*>(xin + (size_t)i * OUTC)[lane];
    float4 r;
    r.x = 0.5f * fmaf(a0, inv, xv.x);
    r.y = 0.5f * fmaf(a1, inv, xv.y);
    r.z = 0.5f * fmaf(a2, inv, xv.z);
    r.w = 0.5f * fmaf(a3, inv, xv.w);
    reinterpret_cast<float4*>(xout + (size_t)i * OUTC)[lane] = r;

    if (write_half) {
        __half2 h0 = __float22half2_rn(make_float2(r.x, r.y));
        __half2 h1 = __float22half2_rn(make_float2(r.z, r.w));
        uint2 hw;
        hw.x = *reinterpret_cast<unsigned*>(&h0);
        hw.y = *reinterpret_cast<unsigned*>(&h1);
        reinterpret_cast<uint2*>(xh_out + (size_t)i * D)[lane] = hw;
    }
}

// ---------------- launch ----------------

extern "C" void kernel_launch(void* const* d_in, const int* in_sizes, int n_in,
                              void* d_out, int out_size) {
    const float* x   = (const float*)d_in[0];
    const int*   p32 = (const int*)d_in[1];
    float*       out = (float*)d_out;

    const int n_nodes = in_sizes[0] / D;      // 50000
    const int n_edges = in_sizes[1] / 2;      // 800000

    const int big      = (n_edges > n_nodes * 16) ? n_edges : n_nodes * 16;
    const int nb_big   = (big + TPB - 1) / TPB;
    const int nb_scan  = (n_nodes + SCAN_B - 1) / SCAN_B;     // 196
    const int nb_scan1 = (n_nodes + 1 + SCAN_B - 1) / SCAN_B; // covers i==n
    const int nb_place = (n_edges + TPB * PLACE_ILP - 1) / (TPB * PLACE_ILP);

    // 0: histogram + slab-0 copies (fp32 + fp16)
    convert_copy_kernel<<<nb_big, TPB>>>(p32, x, out, n_edges, n_nodes);

    // 1-2: rowptr scan (+ cursor init, g_deg reset)
    scan1_kernel<<<nb_scan, SCAN_B>>>(n_nodes);
    scan23_kernel<<<nb_scan1, SCAN_B>>>(n_nodes, n_edges, nb_scan);

    // 3: CSR placement straight from edge_index (4 edges/thread ILP)
    place_kernel<<<nb_place, TPB>>>(p32, n_edges);

    // 4-7: WL iterations (fused pull + combine, fp16 gather, ping-pong)
    {
        int threads = n_nodes * 16;
        int blocks = (threads + TPB - 1) / TPB;
        for (int k = 1; k <= ITERS; k++) {
            pull_kernel<<<blocks, TPB>>>(out + (size_t)(k - 1) * D,
                                         out + (size_t)k * D,
                                         n_nodes, (k - 1) & 1,
                                         (k < ITERS) ? 1 : 0);
        }
    }
}

// round 17
// speedup vs baseline: 2.2388x; 1.0028x over previous
#include <cuda_runtime.h>
#include <cuda_fp16.h>
#include <cstdint>

#define D        64
#define ITERS    4
#define OUTC     ((ITERS + 1) * D)   // 320 output columns
#define N_MAX    50016               // padded
#define E_MAX    800000
#define TPB      256
#define SCAN_B   256
#define PLACE_ILP 2

// -------- scratch (__device__ globals; no allocation allowed) --------
// Zero-initialized at module load; g_deg is re-zeroed by scan23 each call so
// graph replays stay deterministic.
__device__ int    g_deg[N_MAX];          // in-degree
__device__ int    g_rowptr[N_MAX + 1];   // CSR row pointers (by dst)
__device__ int    g_blocksum[SCAN_B];    // scan partials (<=256 blocks)
__device__ int    g_rank[E_MAX];         // edge's rank within its dst row
__device__ int    g_col[E_MAX];          // CSR columns (src grouped by dst)
__device__ __half g_xh0[N_MAX * D];      // fp16 shadow (ping)
__device__ __half g_xh1[N_MAX * D];      // fp16 shadow (pong)

// Block-local dtype detect: majority vote over the first 64 (lo,hi) pairs of
// the edge_index buffer (valid prefix for either dtype). int64 ids < 2^31
// have hi-word == 0; int32 data has random ids there. Returns 1 if int64.
__device__ __forceinline__ int detect_is64(const int* __restrict__ p32,
                                           int* __restrict__ sh_zc) {
    if (threadIdx.x == 0) *sh_zc = 0;
    __syncthreads();
    if (threadIdx.x < 64)
        if (p32[2 * threadIdx.x + 1] == 0) atomicAdd(sh_zc, 1);
    __syncthreads();
    return (*sh_zc >= 48) ? 1 : 0;
}

// ---------------- kernels ----------------

// Fused: degree histogram (edge part; the returned old count is this edge's
// rank within its dst row — saved for atomic-free placement) + copy x into
// out slab 0 (fp32) and g_xh0 (fp16) (node part).
__global__ void convert_copy_kernel(const int* __restrict__ p32,
                                    const float* __restrict__ x,
                                    float* __restrict__ out,
                                    int n_edges, int n_nodes) {
    __shared__ int sh_zc;
    int is64 = detect_is64(p32, &sh_zc);

    int t = blockIdx.x * blockDim.x + threadIdx.x;

    if (t < n_edges) {
        int d = is64 ? p32[2 * ((size_t)n_edges + t)] : p32[n_edges + t];
        g_rank[t] = atomicAdd(&g_deg[d], 1);
    }

    int i = t >> 4;
    int lane = t & 15;                    // 16 lanes x float4 = 64 floats
    if (i < n_nodes) {
        float4 v = reinterpret_cast<const float4*>(x + (size_t)i * D)[lane];
        reinterpret_cast<float4*>(out + (size_t)i * OUTC)[lane] = v;
        __half2 h0 = __float22half2_rn(make_float2(v.x, v.y));
        __half2 h1 = __float22half2_rn(make_float2(v.z, v.w));
        uint2 hw;
        hw.x = *reinterpret_cast<unsigned*>(&h0);
        hw.y = *reinterpret_cast<unsigned*>(&h1);
        reinterpret_cast<uint2*>(g_xh0 + (size_t)i * D)[lane] = hw;
    }
}

// --- exclusive scan of g_deg -> g_rowptr, 2 kernels ---
// scan1: per-block inclusive scan + block totals.
__global__ void scan1_kernel(int n_nodes) {
    __shared__ int sm[SCAN_B];
    int i = blockIdx.x * SCAN_B + threadIdx.x;
    int v = (i < n_nodes) ? g_deg[i] : 0;
    sm[threadIdx.x] = v;
    __syncthreads();
    for (int off = 1; off < SCAN_B; off <<= 1) {
        int t = (threadIdx.x >= off) ? sm[threadIdx.x - off] : 0;
        __syncthreads();
        sm[threadIdx.x] += t;
        __syncthreads();
    }
    if (i < n_nodes) g_rowptr[i] = sm[threadIdx.x] - v;   // exclusive in-block
    if (threadIdx.x == SCAN_B - 1) g_blocksum[blockIdx.x] = sm[threadIdx.x];
}

// scan23: block b adds the scalar prefix sum_{j<b} blocksum[j] (in-block
// reduction, one load per thread) and resets g_deg for the next replay.
__global__ void scan23_kernel(int n_nodes, int n_edges, int nblocks) {
    __shared__ int sm[SCAN_B];
    int b = blockIdx.x;
    int v = (threadIdx.x < b && threadIdx.x < nblocks)
                ? g_blocksum[threadIdx.x] : 0;
    sm[threadIdx.x] = v;
    __syncthreads();
    for (int off = SCAN_B / 2; off > 0; off >>= 1) {
        if (threadIdx.x < off) sm[threadIdx.x] += sm[threadIdx.x + off];
        __syncthreads();
    }
    int boff = sm[0];

    int i = b * SCAN_B + threadIdx.x;
    if (i < n_nodes) {
        g_rowptr[i] += boff;
        g_deg[i] = 0;                     // reset for next replay
    }
    if (i == n_nodes) g_rowptr[n_nodes] = n_edges;
}

// Atomic-free CSR placement: pos = rowptr[dst] + rank (rank captured during
// the histogram). Random L2 read replaces the cursor atomic RMW. ILP=2 keeps
// the grid (1563 blocks) above the 1184-block full-occupancy wave (the R16
// ILP=4 grid of 782 blocks under-filled the chip: occ 55%).
__global__ void place_kernel(const int* __restrict__ p32, int n_edges) {
    __shared__ int sh_zc;
    int is64 = detect_is64(p32, &sh_zc);

    int base = (blockIdx.x * blockDim.x + threadIdx.x) * PLACE_ILP;
    int s[PLACE_ILP], pos[PLACE_ILP];
#pragma unroll
    for (int u = 0; u < PLACE_ILP; u++) {
        int e = base + u;
        if (e < n_edges) {
            int d;
            if (is64) {
                s[u] = p32[2 * e];
                d    = p32[2 * ((size_t)n_edges + e)];
            } else {
                s[u] = p32[e];
                d    = p32[n_edges + e];
            }
            pos[u] = __ldg(&g_rowptr[d]) + g_rank[e];
        }
    }
#pragma unroll
    for (int u = 0; u < PLACE_ILP; u++) {
        int e = base + u;
        if (e < n_edges) g_col[pos[u]] = s[u];
    }
}

// Fused pull + combine, fp16 gather, 16 threads/node. Ping-pong shadows
// resolved in device code via parity.
//   out_k[i] = 0.5 * ( out_{k-1}[i] + (1/max(deg,1)) * sum_j xh[col[j]] )
__global__ void pull_kernel(const float* __restrict__ xin,   // out + (k-1)*D
                            float* __restrict__ xout,        // out + k*D
                            int n_nodes, int parity, int write_half) {
    const __half* __restrict__ xh_in  = parity ? g_xh1 : g_xh0;
    __half*       __restrict__ xh_out = parity ? g_xh0 : g_xh1;

    int t = blockIdx.x * blockDim.x + threadIdx.x;
    int i = t >> 4;
    int lane = t & 15;
    if (i >= n_nodes) return;
    int start = g_rowptr[i];
    int end   = g_rowptr[i + 1];

    float a0 = 0.f, a1 = 0.f, a2 = 0.f, a3 = 0.f;

#pragma unroll 8
    for (int j = start; j < end; j++) {
        int s = __ldg(&g_col[j]);
        uint2 hw = reinterpret_cast<const uint2*>(xh_in + (size_t)s * D)[lane];
        float2 f0 = __half22float2(*reinterpret_cast<__half2*>(&hw.x));
        float2 f1 = __half22float2(*reinterpret_cast<__half2*>(&hw.y));
        a0 += f0.x; a1 += f0.y; a2 += f1.x; a3 += f1.y;
    }

    int deg = end - start;
    float inv = 1.0f / (float)(deg > 0 ? deg : 1);
    float4 xv = reinterpret_cast<const float4*>(xin + (size_t)i * OUTC)[lane];
    float4 r;
    r.x = 0.5f * fmaf(a0, inv, xv.x);
    r.y = 0.5f * fmaf(a1, inv, xv.y);
    r.z = 0.5f * fmaf(a2, inv, xv.z);
    r.w = 0.5f * fmaf(a3, inv, xv.w);
    reinterpret_cast<float4*>(xout + (size_t)i * OUTC)[lane] = r;

    if (write_half) {
        __half2 h0 = __float22half2_rn(make_float2(r.x, r.y));
        __half2 h1 = __float22half2_rn(make_float2(r.z, r.w));
        uint2 hw;
        hw.x = *reinterpret_cast<unsigned*>(&h0);
        hw.y = *reinterpret_cast<unsigned*>(&h1);
        reinterpret_cast<uint2*>(xh_out + (size_t)i * D)[lane] = hw;
    }
}

// ---------------- launch ----------------

extern "C" void kernel_launch(void* const* d_in, const int* in_sizes, int n_in,
                              void* d_out, int out_size) {
    const float* x   = (const float*)d_in[0];
    const int*   p32 = (const int*)d_in[1];
    float*       out = (float*)d_out;

    const int n_nodes = in_sizes[0] / D;      // 50000
    const int n_edges = in_sizes[1] / 2;      // 800000

    const int big      = (n_edges > n_nodes * 16) ? n_edges : n_nodes * 16;
    const int nb_big   = (big + TPB - 1) / TPB;
    const int nb_scan  = (n_nodes + SCAN_B - 1) / SCAN_B;     // 196
    const int nb_scan1 = (n_nodes + 1 + SCAN_B - 1) / SCAN_B; // covers i==n
    const int nb_place = (n_edges + TPB * PLACE_ILP - 1) / (TPB * PLACE_ILP);

    // 0: histogram (+ per-edge rank capture) + slab-0 copies (fp32 + fp16)
    convert_copy_kernel<<<nb_big, TPB>>>(p32, x, out, n_edges, n_nodes);

    // 1-2: rowptr scan (+ g_deg reset)
    scan1_kernel<<<nb_scan, SCAN_B>>>(n_nodes);
    scan23_kernel<<<nb_scan1, SCAN_B>>>(n_nodes, n_edges, nb_scan);

    // 3: atomic-free CSR placement
    place_kernel<<<nb_place, TPB>>>(p32, n_edges);

    // 4-7: WL iterations (fused pull + combine, fp16 gather, ping-pong)
    {
        int threads = n_nodes * 16;
        int blocks = (threads + TPB - 1) / TPB;
        for (int k = 1; k <= ITERS; k++) {
            pull_kernel<<<blocks, TPB>>>(out + (size_t)(k - 1) * D,
                                         out + (size_t)k * D,
                                         n_nodes, (k - 1) & 1,
                                         (k < ITERS) ? 1 : 0);
        }
    }
}